// round 7
// baseline (speedup 1.0000x reference)
#include <cuda_runtime.h>
#include <cstdint>

// Problem constants (fixed shapes from reference)
#define BB 32
#define TT 2048
#define NN 128
#define BN (BB * NN)          // 4096
#define KP 5
#define PMAX 512
#define MINP 2
#define TILES_ELEMS ((size_t)BN * KP * TT)   // 41,943,040
#define EXTRA_ELEMS (BN * KP * 2)            // 40,960

// Scratch (device global — no allocations allowed). +4 pad: gather's
// overlapping float4 load may read 16B past the final series.
__device__ __align__(16) float g_seqs[(size_t)BN * TT + 4];

__device__ __forceinline__ float2 cmul(float2 a, float2 b) {
    return make_float2(a.x * b.x - a.y * b.y, a.x * b.y + a.y * b.x);
}

// bank swizzle for the float2 shared buffer: XOR bits[5:8) into bits[2:5)
__device__ __forceinline__ int sw(int i) { return i ^ (((i >> 5) & 7) << 2); }

// in-register 8-point DFT (natural-order outputs), w8 = exp(-i*pi/4)
__device__ __forceinline__ void dft8(float2* z) {
    float2 e0 = z[0], e1 = z[2], e2 = z[4], e3 = z[6];
    float2 o0 = z[1], o1 = z[3], o2 = z[5], o3 = z[7];
    float2 t0 = make_float2(e0.x + e2.x, e0.y + e2.y);
    float2 t1 = make_float2(e0.x - e2.x, e0.y - e2.y);
    float2 t2 = make_float2(e1.x + e3.x, e1.y + e3.y);
    float2 t3 = make_float2(e1.x - e3.x, e1.y - e3.y);
    float2 E0 = make_float2(t0.x + t2.x, t0.y + t2.y);
    float2 E2 = make_float2(t0.x - t2.x, t0.y - t2.y);
    float2 E1 = make_float2(t1.x + t3.y, t1.y - t3.x);
    float2 E3 = make_float2(t1.x - t3.y, t1.y + t3.x);
    t0 = make_float2(o0.x + o2.x, o0.y + o2.y);
    t1 = make_float2(o0.x - o2.x, o0.y - o2.y);
    t2 = make_float2(o1.x + o3.x, o1.y + o3.y);
    t3 = make_float2(o1.x - o3.x, o1.y - o3.y);
    float2 O0 = make_float2(t0.x + t2.x, t0.y + t2.y);
    float2 O2 = make_float2(t0.x - t2.x, t0.y - t2.y);
    float2 O1 = make_float2(t1.x + t3.y, t1.y - t3.x);
    float2 O3 = make_float2(t1.x - t3.y, t1.y + t3.x);
    const float C = 0.70710678118654752f;
    float2 P1 = make_float2(C * (O1.x + O1.y), C * (O1.y - O1.x));   // w8^1 * O1
    float2 P2 = make_float2(O2.y, -O2.x);                            // w8^2 * O2 = -i*O2
    float2 P3 = make_float2(C * (O3.y - O3.x), -C * (O3.x + O3.y));  // w8^3 * O3
    z[0] = make_float2(E0.x + O0.x, E0.y + O0.y);
    z[4] = make_float2(E0.x - O0.x, E0.y - O0.y);
    z[1] = make_float2(E1.x + P1.x, E1.y + P1.y);
    z[5] = make_float2(E1.x - P1.x, E1.y - P1.y);
    z[2] = make_float2(E2.x + P2.x, E2.y + P2.y);
    z[6] = make_float2(E2.x - P2.x, E2.y - P2.y);
    z[3] = make_float2(E3.x + P3.x, E3.y + P3.y);
    z[7] = make_float2(E3.x - P3.x, E3.y - P3.y);
}

// twiddle-multiply b=1..7 by chained cmul from single w1 (saves 6 LDS/stage)
__device__ __forceinline__ void twchain(float2* v, float2 w1) {
    float2 w = w1;
    v[1] = cmul(v[1], w);
    w = cmul(w, w1); v[2] = cmul(v[2], w);
    w = cmul(w, w1); v[3] = cmul(v[3], w);
    w = cmul(w, w1); v[4] = cmul(v[4], w);
    w = cmul(w, w1); v[5] = cmul(v[5], w);
    w = cmul(w, w1); v[6] = cmul(v[6], w);
    w = cmul(w, w1); v[7] = cmul(v[7], w);
}

// in-register 4-point DFT, w4 = -i
__device__ __forceinline__ void dft4(const float2* z, float2* Z) {
    float2 a = make_float2(z[0].x - z[2].x, z[0].y - z[2].y);
    float2 b = make_float2(z[1].x - z[3].x, z[1].y - z[3].y);
    Z[0] = make_float2(z[0].x + z[1].x + z[2].x + z[3].x,
                       z[0].y + z[1].y + z[2].y + z[3].y);
    Z[1] = make_float2(a.x + b.y, a.y - b.x);
    Z[2] = make_float2(z[0].x - z[1].x + z[2].x - z[3].x,
                       z[0].y - z[1].y + z[2].y - z[3].y);
    Z[3] = make_float2(a.x - b.y, a.y + b.x);
}

// packed-real conjugate split -> mag^2 for bin k (A at mag[k-1], B at mag[1023+k])
__device__ __forceinline__ void putmag(float* mag, int k, float2 Zk, float2 Zc) {
    float x1r = Zk.x + Zc.x, x1i = Zk.y - Zc.y;
    float x2r = Zk.y + Zc.y, x2i = Zc.x - Zk.x;
    mag[k - 1]    = x1r * x1r + x1i * x1i;
    mag[1023 + k] = x2r * x2r + x2i * x2i;
}

// One gather row, compile-time source misalignment OFS = start & 3.
// Aligned overlapping LDG.128 + register recombine + STG.128 streaming store.
template <int OFS>
__device__ __forceinline__ void gather_row(const float4* __restrict__ s4,
                                           float4* __restrict__ dst4,
                                           int vlast, int rem, int tid) {
#pragma unroll
    for (int it = 0; it < 2; ++it) {
        int v = tid + it * 256;             // float4 index 0..511
        float4 o = make_float4(0.f, 0.f, 0.f, 0.f);
        if (v <= vlast) {
            float4 a = s4[v];
            if (OFS == 0) {
                o = a;
            } else {
                float4 b = s4[v + 1];
                if (OFS == 1) o = make_float4(a.y, a.z, a.w, b.x);
                if (OFS == 2) o = make_float4(a.z, a.w, b.x, b.y);
                if (OFS == 3) o = make_float4(a.w, b.x, b.y, b.z);
            }
            if (v == vlast) {               // straddling vector: zero the tail
                if (rem < 4) o.w = 0.f;
                if (rem < 3) o.z = 0.f;
                if (rem < 2) o.y = 0.f;
            }
        }
        __stcs(dst4 + v, o);
    }
}

// ---------------------------------------------------------------------------
// Kernel 1: transpose x[b,t,n] -> seqs[b*N+n, t], 64x64 tiles, float4 both ways
// ---------------------------------------------------------------------------
__global__ void __launch_bounds__(256)
transpose_kernel(const float* __restrict__ x, float* __restrict__ seqs) {
    __shared__ float tile[64][65];
    const int b = blockIdx.z;
    const int tBase = blockIdx.x * 64;   // along T
    const int nBase = blockIdx.y * 64;   // along N
    const int tid = threadIdx.x;
    const float* src = x + (size_t)b * TT * NN;

#pragma unroll
    for (int it = 0; it < 4; ++it) {
        int idx = tid + it * 256;            // 0..1023
        int r = idx >> 4;                    // t offset 0..63
        int c = idx & 15;                    // float4 col along N
        float4 v = *reinterpret_cast<const float4*>(
            src + (size_t)(tBase + r) * NN + nBase + c * 4);
        tile[c * 4 + 0][r] = v.x;
        tile[c * 4 + 1][r] = v.y;
        tile[c * 4 + 2][r] = v.z;
        tile[c * 4 + 3][r] = v.w;
    }
    __syncthreads();
#pragma unroll
    for (int it = 0; it < 4; ++it) {
        int idx = tid + it * 256;
        int r = idx >> 4;                    // n offset 0..63
        int c = idx & 15;                    // float4 col along T
        float4 v;
        v.x = tile[r][c * 4 + 0];
        v.y = tile[r][c * 4 + 1];
        v.z = tile[r][c * 4 + 2];
        v.w = tile[r][c * 4 + 3];
        *reinterpret_cast<float4*>(
            seqs + (size_t)(b * NN + nBase + r) * TT + tBase + c * 4) = v;
    }
}

// ---------------------------------------------------------------------------
// Kernel 2 (fused): packed 2-real 2048-pt FFT (radix 8*8*8*4, register
// butterflies, chained twiddles, one 16KB exchange buffer), conjugate split
// -> mag^2 in registers, register top-5 + shuffle merge, period math, fused
// vectorized tile gather. One block = 2 series.
// ---------------------------------------------------------------------------
__global__ void __launch_bounds__(256)
fft_topk_gather_kernel(const float* __restrict__ seqs,
                       float* __restrict__ tiles,
                       float* __restrict__ out_extra,   // periods then cycles
                       int write_extras) {
    __shared__ float2 buf[2048];          // 16 KB exchange buffer (reused as mag)
    __shared__ float2 tw[256];            // tw[m] = exp(-2*pi*i*m/2048), m<256
    __shared__ float  wbv[8];             // per-warp best value
    __shared__ int    wbi[8];             // per-warp best index
    __shared__ int    swin[2];            // per-half winning bin this round
    __shared__ int    stake[2 * KP];

    const int pair = blockIdx.x;          // 0..2047
    const int tid  = threadIdx.x;
    const int lane = tid & 31;
    const int wid  = tid >> 5;
    const float* sa = seqs + (size_t)(pair * 2) * TT;
    const float* sb = sa + TT;

    // Stage 1 inputs (global, coalesced) — issue before tw init for overlap
    float2 v[8];
#pragma unroll
    for (int a = 0; a < 8; ++a)
        v[a] = make_float2(sa[tid + 256 * a], sb[tid + 256 * a]);

    {
        float sn, cs; sincospif(-(float)tid / 1024.0f, &sn, &cs);
        tw[tid] = make_float2(cs, sn);
    }
    __syncthreads();

    // Stage 1: x[256a + t] -> z1[b][t] = DFT8_a * w2048^{t*b}  (w1 = tw[tid])
    dft8(v);
    twchain(v, tw[tid]);
#pragma unroll
    for (int b = 0; b < 8; ++b) buf[sw(b * 256 + tid)] = v[b];
    __syncthreads();

    // Stage 2: per (b, t2): DFT8 over a2 (stride 32), w1 = tw[8*t2]; in-place
    {
        const int b = tid >> 5, t2 = tid & 31;
        const int base = b * 256 + t2;
#pragma unroll
        for (int a2 = 0; a2 < 8; ++a2) v[a2] = buf[sw(base + 32 * a2)];
        dft8(v);
        twchain(v, tw[8 * t2]);
#pragma unroll
        for (int b2 = 0; b2 < 8; ++b2) buf[sw(base + 32 * b2)] = v[b2];
    }
    __syncthreads();

    // Stage 3: per (b, b2, t3): DFT8 over a3 (stride 4), w1 = tw[64*t3];
    // output re-laid out group-major: idx = (64*b3 + 8*b2 + b)*4 + t3
    {
        const int b = tid >> 5, b2 = (tid >> 2) & 7, t3 = tid & 3;
        const int base = b * 256 + b2 * 32 + t3;
#pragma unroll
        for (int a3 = 0; a3 < 8; ++a3) v[a3] = buf[sw(base + 4 * a3)];
        dft8(v);
        twchain(v, tw[64 * t3]);
        __syncthreads();                   // layout change: all reads before writes
#pragma unroll
        for (int b3 = 0; b3 < 8; ++b3)
            buf[sw((64 * b3 + 8 * b2 + b) * 4 + t3)] = v[b3];
    }
    __syncthreads();

    // Stage 4 + conjugate split + mag^2 (mag overlays buf as float[2048]).
    float* mag = reinterpret_cast<float*>(buf);
    {
        const int rA = tid;
        const int rB = (tid == 0) ? 256 : 512 - tid;
        float2 za[4], zb[4];
#pragma unroll
        for (int t3 = 0; t3 < 4; ++t3) za[t3] = buf[sw(rA * 4 + t3)];
#pragma unroll
        for (int t3 = 0; t3 < 4; ++t3) zb[t3] = buf[sw(rB * 4 + t3)];
        __syncthreads();                   // all reads done before mag overwrites buf
        float2 ZA[4], ZB[4];
        dft4(za, ZA);                      // ZA[c3] = Z[512*c3 + rA]
        dft4(zb, ZB);                      // ZB[c3] = Z[512*c3 + rB]
        if (tid == 0) {
            putmag(mag, 512,  ZA[1], ZA[3]);
            putmag(mag, 1024, ZA[2], ZA[2]);
            putmag(mag, 256,  ZB[0], ZB[3]);
            putmag(mag, 768,  ZB[1], ZB[2]);
        } else {
            putmag(mag, tid,        ZA[0], ZB[3]);   // conj(t)      = 2048-t
            putmag(mag, 512 + tid,  ZA[1], ZB[2]);   // conj(512+t)  = 1536-t
            putmag(mag, 512 - tid,  ZB[0], ZA[3]);   // conj(512-t)  = 1536+t
            putmag(mag, 1024 - tid, ZB[1], ZA[2]);   // conj(1024-t) = 1024+t
        }
    }
    __syncthreads();

    // ---- Register top-5 ----
    // Each thread scans its 8 bins once, keeping a sorted top-5 in registers.
    // threads [0,128) = series A, [128,256) = series B.
    const int half = tid >> 7;
    const int ht   = tid & 127;
    const float* magp = mag + half * 1024;
    const int bn = pair * 2 + half;

    float t0v = -1.f, t1v = -1.f, t2v = -1.f, t3v = -1.f, t4v = -1.f;
    int   t0i = 0,    t1i = 0,    t2i = 0,    t3i = 0,    t4i = 0;
#pragma unroll
    for (int j = 0; j < 8; ++j) {
        int id = ht + j * 128;             // increasing idx -> ties keep earlier
        float vv = magp[id];
        if (vv > t4v) {
            if (vv > t0v)      { t4v=t3v;t4i=t3i; t3v=t2v;t3i=t2i; t2v=t1v;t2i=t1i; t1v=t0v;t1i=t0i; t0v=vv;t0i=id; }
            else if (vv > t1v) { t4v=t3v;t4i=t3i; t3v=t2v;t3i=t2i; t2v=t1v;t2i=t1i; t1v=vv;t1i=id; }
            else if (vv > t2v) { t4v=t3v;t4i=t3i; t3v=t2v;t3i=t2i; t2v=vv;t2i=id; }
            else if (vv > t3v) { t4v=t3v;t4i=t3i; t3v=vv;t3i=id; }
            else               { t4v=vv;t4i=id; }
        }
    }

    // 5 merge rounds: warp shuffle-reduce heads -> per-warp best -> leader picks
    int h = 0;                             // head into my sorted top-5
    for (int kk = 0; kk < KP; ++kk) {
        float cv = -2.0f; int ci = 1 << 29;
        if      (h == 0) { cv = t0v; ci = t0i; }
        else if (h == 1) { cv = t1v; ci = t1i; }
        else if (h == 2) { cv = t2v; ci = t2i; }
        else if (h == 3) { cv = t3v; ci = t3i; }
        else if (h == 4) { cv = t4v; ci = t4i; }
        float bv = cv; int bi = ci;
#pragma unroll
        for (int off = 16; off; off >>= 1) {
            float v2 = __shfl_down_sync(0xffffffffu, bv, off);
            int   b2 = __shfl_down_sync(0xffffffffu, bi, off);
            if (v2 > bv || (v2 == bv && b2 < bi)) { bv = v2; bi = b2; }
        }
        if (lane == 0) { wbv[wid] = bv; wbi[wid] = bi; }
        __syncthreads();
        if ((tid & 127) == 0) {            // tid 0 (half A) and tid 128 (half B)
            int base = half * 4;
            float gv = wbv[base]; int gi = wbi[base];
#pragma unroll
            for (int w = 1; w < 4; ++w) {
                float v2 = wbv[base + w]; int b2 = wbi[base + w];
                if (v2 > gv || (v2 == gv && b2 < gi)) { gv = v2; gi = b2; }
            }
            swin[half] = gi;
            int kidx = gi + 1;
            int period = TT / kidx;
            period = period < PMAX ? period : PMAX;
            period = period > MINP ? period : MINP;
            int cyc = TT / period; if (cyc < 1) cyc = 1;
            stake[half * KP + kk] = cyc * period;
            if (write_extras) {
                out_extra[bn * KP + kk]                   = (float)period;
                out_extra[(size_t)BN * KP + bn * KP + kk] = (float)cyc;
            }
        }
        __syncthreads();
        if (swin[half] == ci) ++h;         // winner's owner advances its head
    }

    // Fused gather epilogue: 10 tile rows. start is uniform per row, so the
    // source misalignment (start & 3) is handled by a 4-way uniform switch:
    // two overlapping aligned LDG.128 + compile-time register recombine +
    // one STG.128 streaming store per float4.
#pragma unroll 1
    for (int r = 0; r < 2 * KP; ++r) {
        const int h2 = r / KP;
        const int tk = stake[r];
        const int start = TT - tk;
        const int vlast = (tk - 1) >> 2;           // last vector with any data
        const int rem   = tk - 4 * vlast;          // valid elems in it (1..4)
        const float4* s4 = reinterpret_cast<const float4*>(
            seqs + (size_t)(pair * 2 + h2) * TT) + (start >> 2);
        float4* dst4 = reinterpret_cast<float4*>(
            tiles + ((size_t)pair * 2 * KP + r) * TT);
        switch (start & 3) {
            case 0: gather_row<0>(s4, dst4, vlast, rem, tid); break;
            case 1: gather_row<1>(s4, dst4, vlast, rem, tid); break;
            case 2: gather_row<2>(s4, dst4, vlast, rem, tid); break;
            default: gather_row<3>(s4, dst4, vlast, rem, tid); break;
        }
    }
}

// ---------------------------------------------------------------------------
extern "C" void kernel_launch(void* const* d_in, const int* in_sizes, int n_in,
                              void* d_out, int out_size) {
    const float* x = (const float*)d_in[0];
    float* out = (float*)d_out;

    float* seqs;
    cudaGetSymbolAddress((void**)&seqs, g_seqs);

    // 1) transpose to [BN, T]
    {
        dim3 grid(TT / 64, NN / 64, BB);
        transpose_kernel<<<grid, 256>>>(x, seqs);
    }

    // 2) fused FFT + top-k + period math + tile gather
    {
        int write_extras = ((size_t)out_size >= (TILES_ELEMS + EXTRA_ELEMS)) ? 1 : 0;
        float* extra = out + TILES_ELEMS;
        fft_topk_gather_kernel<<<BN / 2, 256>>>(seqs, out, extra, write_extras);
    }
}

// round 8
// speedup vs baseline: 1.0367x; 1.0367x over previous
#include <cuda_runtime.h>
#include <cstdint>

// Problem constants (fixed shapes from reference)
#define BB 32
#define TT 2048
#define NN 128
#define BN (BB * NN)          // 4096
#define KP 5
#define PMAX 512
#define MINP 2
#define TILES_ELEMS ((size_t)BN * KP * TT)   // 41,943,040
#define EXTRA_ELEMS (BN * KP * 2)            // 40,960

// Scratch (device global — no allocations allowed)
__device__ __align__(16) float g_seqs[(size_t)BN * TT];

__device__ __forceinline__ float2 cmul(float2 a, float2 b) {
    return make_float2(a.x * b.x - a.y * b.y, a.x * b.y + a.y * b.x);
}

// bank swizzle for the float2 shared buffer: XOR bits[5:8) into bits[2:5)
__device__ __forceinline__ int sw(int i) { return i ^ (((i >> 5) & 7) << 2); }

// in-register 8-point DFT (natural-order outputs), w8 = exp(-i*pi/4)
__device__ __forceinline__ void dft8(float2* z) {
    float2 e0 = z[0], e1 = z[2], e2 = z[4], e3 = z[6];
    float2 o0 = z[1], o1 = z[3], o2 = z[5], o3 = z[7];
    float2 t0 = make_float2(e0.x + e2.x, e0.y + e2.y);
    float2 t1 = make_float2(e0.x - e2.x, e0.y - e2.y);
    float2 t2 = make_float2(e1.x + e3.x, e1.y + e3.y);
    float2 t3 = make_float2(e1.x - e3.x, e1.y - e3.y);
    float2 E0 = make_float2(t0.x + t2.x, t0.y + t2.y);
    float2 E2 = make_float2(t0.x - t2.x, t0.y - t2.y);
    float2 E1 = make_float2(t1.x + t3.y, t1.y - t3.x);
    float2 E3 = make_float2(t1.x - t3.y, t1.y + t3.x);
    t0 = make_float2(o0.x + o2.x, o0.y + o2.y);
    t1 = make_float2(o0.x - o2.x, o0.y - o2.y);
    t2 = make_float2(o1.x + o3.x, o1.y + o3.y);
    t3 = make_float2(o1.x - o3.x, o1.y - o3.y);
    float2 O0 = make_float2(t0.x + t2.x, t0.y + t2.y);
    float2 O2 = make_float2(t0.x - t2.x, t0.y - t2.y);
    float2 O1 = make_float2(t1.x + t3.y, t1.y - t3.x);
    float2 O3 = make_float2(t1.x - t3.y, t1.y + t3.x);
    const float C = 0.70710678118654752f;
    float2 P1 = make_float2(C * (O1.x + O1.y), C * (O1.y - O1.x));   // w8^1 * O1
    float2 P2 = make_float2(O2.y, -O2.x);                            // w8^2 * O2 = -i*O2
    float2 P3 = make_float2(C * (O3.y - O3.x), -C * (O3.x + O3.y));  // w8^3 * O3
    z[0] = make_float2(E0.x + O0.x, E0.y + O0.y);
    z[4] = make_float2(E0.x - O0.x, E0.y - O0.y);
    z[1] = make_float2(E1.x + P1.x, E1.y + P1.y);
    z[5] = make_float2(E1.x - P1.x, E1.y - P1.y);
    z[2] = make_float2(E2.x + P2.x, E2.y + P2.y);
    z[6] = make_float2(E2.x - P2.x, E2.y - P2.y);
    z[3] = make_float2(E3.x + P3.x, E3.y + P3.y);
    z[7] = make_float2(E3.x - P3.x, E3.y - P3.y);
}

// twiddle-multiply b=1..7 by chained cmul from single w1 (saves 6 LDS/stage)
__device__ __forceinline__ void twchain(float2* v, float2 w1) {
    float2 w = w1;
    v[1] = cmul(v[1], w);
    w = cmul(w, w1); v[2] = cmul(v[2], w);
    w = cmul(w, w1); v[3] = cmul(v[3], w);
    w = cmul(w, w1); v[4] = cmul(v[4], w);
    w = cmul(w, w1); v[5] = cmul(v[5], w);
    w = cmul(w, w1); v[6] = cmul(v[6], w);
    w = cmul(w, w1); v[7] = cmul(v[7], w);
}

// in-register 4-point DFT, w4 = -i
__device__ __forceinline__ void dft4(const float2* z, float2* Z) {
    float2 a = make_float2(z[0].x - z[2].x, z[0].y - z[2].y);
    float2 b = make_float2(z[1].x - z[3].x, z[1].y - z[3].y);
    Z[0] = make_float2(z[0].x + z[1].x + z[2].x + z[3].x,
                       z[0].y + z[1].y + z[2].y + z[3].y);
    Z[1] = make_float2(a.x + b.y, a.y - b.x);
    Z[2] = make_float2(z[0].x - z[1].x + z[2].x - z[3].x,
                       z[0].y - z[1].y + z[2].y - z[3].y);
    Z[3] = make_float2(a.x - b.y, a.y + b.x);
}

// packed-real conjugate split -> mag^2 for bin k (A at mag[k-1], B at mag[1023+k])
__device__ __forceinline__ void putmag(float* mag, int k, float2 Zk, float2 Zc) {
    float x1r = Zk.x + Zc.x, x1i = Zk.y - Zc.y;
    float x2r = Zk.y + Zc.y, x2i = Zc.x - Zk.x;
    mag[k - 1]    = x1r * x1r + x1i * x1i;
    mag[1023 + k] = x2r * x2r + x2i * x2i;
}

// One gather row from the SMEM series copy. OFS = start & 3 (uniform).
// take >= 1537 guarantees vlast >= 384, so the first 256 vectors need no
// predicate at all; only the second half carries bound + tail zeroing.
template <int OFS>
__device__ __forceinline__ void gather_row_s(const float4* __restrict__ s4,
                                             float4* __restrict__ dst4,
                                             int vlast, int rem, int tid) {
    {   // v in [0,256): always fully valid
        int v = tid;
        float4 a = s4[v];
        float4 o;
        if (OFS == 0) o = a;
        else {
            float4 b = s4[v + 1];
            if (OFS == 1) o = make_float4(a.y, a.z, a.w, b.x);
            if (OFS == 2) o = make_float4(a.z, a.w, b.x, b.y);
            if (OFS == 3) o = make_float4(a.w, b.x, b.y, b.z);
        }
        __stcs(dst4 + v, o);
    }
    {   // v in [256,512): bound + tail
        int v = tid + 256;
        float4 o = make_float4(0.f, 0.f, 0.f, 0.f);
        if (v <= vlast) {
            float4 a = s4[v];
            if (OFS == 0) o = a;
            else {
                float4 b = s4[v + 1];
                if (OFS == 1) o = make_float4(a.y, a.z, a.w, b.x);
                if (OFS == 2) o = make_float4(a.z, a.w, b.x, b.y);
                if (OFS == 3) o = make_float4(a.w, b.x, b.y, b.z);
            }
            if (v == vlast) {              // straddling vector: zero the tail
                if (rem < 4) o.w = 0.f;
                if (rem < 3) o.z = 0.f;
                if (rem < 2) o.y = 0.f;
            }
        }
        __stcs(dst4 + v, o);
    }
}

// ---------------------------------------------------------------------------
// Kernel 1: transpose x[b,t,n] -> seqs[b*N+n, t], 64x64 tiles, float4 both ways
// ---------------------------------------------------------------------------
__global__ void __launch_bounds__(256)
transpose_kernel(const float* __restrict__ x, float* __restrict__ seqs) {
    __shared__ float tile[64][65];
    const int b = blockIdx.z;
    const int tBase = blockIdx.x * 64;   // along T
    const int nBase = blockIdx.y * 64;   // along N
    const int tid = threadIdx.x;
    const float* src = x + (size_t)b * TT * NN;

#pragma unroll
    for (int it = 0; it < 4; ++it) {
        int idx = tid + it * 256;            // 0..1023
        int r = idx >> 4;                    // t offset 0..63
        int c = idx & 15;                    // float4 col along N
        float4 v = *reinterpret_cast<const float4*>(
            src + (size_t)(tBase + r) * NN + nBase + c * 4);
        tile[c * 4 + 0][r] = v.x;
        tile[c * 4 + 1][r] = v.y;
        tile[c * 4 + 2][r] = v.z;
        tile[c * 4 + 3][r] = v.w;
    }
    __syncthreads();
#pragma unroll
    for (int it = 0; it < 4; ++it) {
        int idx = tid + it * 256;
        int r = idx >> 4;                    // n offset 0..63
        int c = idx & 15;                    // float4 col along T
        float4 v;
        v.x = tile[r][c * 4 + 0];
        v.y = tile[r][c * 4 + 1];
        v.z = tile[r][c * 4 + 2];
        v.w = tile[r][c * 4 + 3];
        *reinterpret_cast<float4*>(
            seqs + (size_t)(b * NN + nBase + r) * TT + tBase + c * 4) = v;
    }
}

// ---------------------------------------------------------------------------
// Kernel 2 (fused): packed 2-real 2048-pt FFT (radix 8*8*8*4, register
// butterflies, chained twiddles, one 16KB exchange buffer), conjugate split
// -> mag^2 in registers, register top-5 + shuffle merge, period math, then
// the 2 series are re-staged into the (now free) smem buffer and the 10 tile
// rows are written with LDS.128-recombine + STG.128 streaming stores.
// One block = 2 series.
// ---------------------------------------------------------------------------
__global__ void __launch_bounds__(256)
fft_topk_gather_kernel(const float* __restrict__ seqs,
                       float* __restrict__ tiles,
                       float* __restrict__ out_extra,   // periods then cycles
                       int write_extras) {
    __shared__ __align__(16) float2 buf[2052];  // 16KB+pad: exchange / mag / series copy
    __shared__ float2 tw[256];            // tw[m] = exp(-2*pi*i*m/2048), m<256
    __shared__ float  wbv[8];             // per-warp best value
    __shared__ int    wbi[8];             // per-warp best index
    __shared__ int    swin[2];            // per-half winning bin this round
    __shared__ int    stake[2 * KP];

    const int pair = blockIdx.x;          // 0..2047
    const int tid  = threadIdx.x;
    const int lane = tid & 31;
    const int wid  = tid >> 5;
    const float* sa = seqs + (size_t)(pair * 2) * TT;
    const float* sb = sa + TT;

    // Stage 1 inputs (global, coalesced) — issue before tw init for overlap
    float2 v[8];
#pragma unroll
    for (int a = 0; a < 8; ++a)
        v[a] = make_float2(sa[tid + 256 * a], sb[tid + 256 * a]);

    {
        float sn, cs; sincospif(-(float)tid / 1024.0f, &sn, &cs);
        tw[tid] = make_float2(cs, sn);
    }
    __syncthreads();

    // Stage 1: x[256a + t] -> z1[b][t] = DFT8_a * w2048^{t*b}  (w1 = tw[tid])
    dft8(v);
    twchain(v, tw[tid]);
#pragma unroll
    for (int b = 0; b < 8; ++b) buf[sw(b * 256 + tid)] = v[b];
    __syncthreads();

    // Stage 2: per (b, t2): DFT8 over a2 (stride 32), w1 = tw[8*t2]; in-place
    {
        const int b = tid >> 5, t2 = tid & 31;
        const int base = b * 256 + t2;
#pragma unroll
        for (int a2 = 0; a2 < 8; ++a2) v[a2] = buf[sw(base + 32 * a2)];
        dft8(v);
        twchain(v, tw[8 * t2]);
#pragma unroll
        for (int b2 = 0; b2 < 8; ++b2) buf[sw(base + 32 * b2)] = v[b2];
    }
    __syncthreads();

    // Stage 3: per (b, b2, t3): DFT8 over a3 (stride 4), w1 = tw[64*t3];
    // output re-laid out group-major: idx = (64*b3 + 8*b2 + b)*4 + t3
    {
        const int b = tid >> 5, b2 = (tid >> 2) & 7, t3 = tid & 3;
        const int base = b * 256 + b2 * 32 + t3;
#pragma unroll
        for (int a3 = 0; a3 < 8; ++a3) v[a3] = buf[sw(base + 4 * a3)];
        dft8(v);
        twchain(v, tw[64 * t3]);
        __syncthreads();                   // layout change: all reads before writes
#pragma unroll
        for (int b3 = 0; b3 < 8; ++b3)
            buf[sw((64 * b3 + 8 * b2 + b) * 4 + t3)] = v[b3];
    }
    __syncthreads();

    // Stage 4 + conjugate split + mag^2 (mag overlays buf as float[2048]).
    float* mag = reinterpret_cast<float*>(buf);
    {
        const int rA = tid;
        const int rB = (tid == 0) ? 256 : 512 - tid;
        float2 za[4], zb[4];
#pragma unroll
        for (int t3 = 0; t3 < 4; ++t3) za[t3] = buf[sw(rA * 4 + t3)];
#pragma unroll
        for (int t3 = 0; t3 < 4; ++t3) zb[t3] = buf[sw(rB * 4 + t3)];
        __syncthreads();                   // all reads done before mag overwrites buf
        float2 ZA[4], ZB[4];
        dft4(za, ZA);                      // ZA[c3] = Z[512*c3 + rA]
        dft4(zb, ZB);                      // ZB[c3] = Z[512*c3 + rB]
        if (tid == 0) {
            putmag(mag, 512,  ZA[1], ZA[3]);
            putmag(mag, 1024, ZA[2], ZA[2]);
            putmag(mag, 256,  ZB[0], ZB[3]);
            putmag(mag, 768,  ZB[1], ZB[2]);
        } else {
            putmag(mag, tid,        ZA[0], ZB[3]);   // conj(t)      = 2048-t
            putmag(mag, 512 + tid,  ZA[1], ZB[2]);   // conj(512+t)  = 1536-t
            putmag(mag, 512 - tid,  ZB[0], ZA[3]);   // conj(512-t)  = 1536+t
            putmag(mag, 1024 - tid, ZB[1], ZA[2]);   // conj(1024-t) = 1024+t
        }
    }
    __syncthreads();

    // ---- Register top-5 ----
    // Each thread scans its 8 bins once, keeping a sorted top-5 in registers.
    // threads [0,128) = series A, [128,256) = series B.
    const int half = tid >> 7;
    const int ht   = tid & 127;
    const float* magp = mag + half * 1024;
    const int bn = pair * 2 + half;

    float t0v = -1.f, t1v = -1.f, t2v = -1.f, t3v = -1.f, t4v = -1.f;
    int   t0i = 0,    t1i = 0,    t2i = 0,    t3i = 0,    t4i = 0;
#pragma unroll
    for (int j = 0; j < 8; ++j) {
        int id = ht + j * 128;             // increasing idx -> ties keep earlier
        float vv = magp[id];
        if (vv > t4v) {
            if (vv > t0v)      { t4v=t3v;t4i=t3i; t3v=t2v;t3i=t2i; t2v=t1v;t2i=t1i; t1v=t0v;t1i=t0i; t0v=vv;t0i=id; }
            else if (vv > t1v) { t4v=t3v;t4i=t3i; t3v=t2v;t3i=t2i; t2v=t1v;t2i=t1i; t1v=vv;t1i=id; }
            else if (vv > t2v) { t4v=t3v;t4i=t3i; t3v=t2v;t3i=t2i; t2v=vv;t2i=id; }
            else if (vv > t3v) { t4v=t3v;t4i=t3i; t3v=vv;t3i=id; }
            else               { t4v=vv;t4i=id; }
        }
    }

    // 5 merge rounds: warp shuffle-reduce heads -> per-warp best -> leader picks
    int h = 0;                             // head into my sorted top-5
    for (int kk = 0; kk < KP; ++kk) {
        float cv = -2.0f; int ci = 1 << 29;
        if      (h == 0) { cv = t0v; ci = t0i; }
        else if (h == 1) { cv = t1v; ci = t1i; }
        else if (h == 2) { cv = t2v; ci = t2i; }
        else if (h == 3) { cv = t3v; ci = t3i; }
        else if (h == 4) { cv = t4v; ci = t4i; }
        float bv = cv; int bi = ci;
#pragma unroll
        for (int off = 16; off; off >>= 1) {
            float v2 = __shfl_down_sync(0xffffffffu, bv, off);
            int   b2 = __shfl_down_sync(0xffffffffu, bi, off);
            if (v2 > bv || (v2 == bv && b2 < bi)) { bv = v2; bi = b2; }
        }
        if (lane == 0) { wbv[wid] = bv; wbi[wid] = bi; }
        __syncthreads();
        if ((tid & 127) == 0) {            // tid 0 (half A) and tid 128 (half B)
            int base = half * 4;
            float gv = wbv[base]; int gi = wbi[base];
#pragma unroll
            for (int w = 1; w < 4; ++w) {
                float v2 = wbv[base + w]; int b2 = wbi[base + w];
                if (v2 > gv || (v2 == gv && b2 < gi)) { gv = v2; gi = b2; }
            }
            swin[half] = gi;
            int kidx = gi + 1;
            int period = TT / kidx;
            period = period < PMAX ? period : PMAX;
            period = period > MINP ? period : MINP;
            int cyc = TT / period; if (cyc < 1) cyc = 1;
            stake[half * KP + kk] = cyc * period;
            if (write_extras) {
                out_extra[bn * KP + kk]                   = (float)period;
                out_extra[(size_t)BN * KP + bn * KP + kk] = (float)cyc;
            }
        }
        __syncthreads();
        if (swin[half] == ci) ++h;         // winner's owner advances its head
    }

    // ---- Re-stage both series into smem (buf is dead after top-k) ----
    // 16 KB contiguous: scopy[0..2048) = series A, [2048..4096) = series B.
    float* scopy = reinterpret_cast<float*>(buf);
    {
        const float4* g4 = reinterpret_cast<const float4*>(sa);   // L2-hot
        float4* c4 = reinterpret_cast<float4*>(scopy);
#pragma unroll
        for (int j = 0; j < 4; ++j) c4[tid + 256 * j] = g4[tid + 256 * j];
        if (tid < 2) c4[1024 + tid] = make_float4(0.f, 0.f, 0.f, 0.f);  // pad
    }
    __syncthreads();

    // ---- Gather epilogue: 10 tile rows from smem, STG.128 stores ----
    // start is uniform per row -> misalignment handled by uniform 4-way switch
    // with compile-time recombine of two aligned LDS.128.
#pragma unroll 1
    for (int r = 0; r < 2 * KP; ++r) {
        const int h2 = (r >= KP);
        const int tk = stake[r];
        const int start = TT - tk;                 // <= 511
        const int vlast = (tk - 1) >> 2;           // >= 384
        const int rem   = tk - 4 * vlast;          // valid elems in last vec (1..4)
        const float4* s4 = reinterpret_cast<const float4*>(
            scopy + h2 * TT + (start & ~3));
        float4* dst4 = reinterpret_cast<float4*>(
            tiles + ((size_t)pair * 2 * KP + r) * TT);
        switch (start & 3) {
            case 0:  gather_row_s<0>(s4, dst4, vlast, rem, tid); break;
            case 1:  gather_row_s<1>(s4, dst4, vlast, rem, tid); break;
            case 2:  gather_row_s<2>(s4, dst4, vlast, rem, tid); break;
            default: gather_row_s<3>(s4, dst4, vlast, rem, tid); break;
        }
    }
}

// ---------------------------------------------------------------------------
extern "C" void kernel_launch(void* const* d_in, const int* in_sizes, int n_in,
                              void* d_out, int out_size) {
    const float* x = (const float*)d_in[0];
    float* out = (float*)d_out;

    float* seqs;
    cudaGetSymbolAddress((void**)&seqs, g_seqs);

    // 1) transpose to [BN, T]
    {
        dim3 grid(TT / 64, NN / 64, BB);
        transpose_kernel<<<grid, 256>>>(x, seqs);
    }

    // 2) fused FFT + top-k + period math + tile gather
    {
        int write_extras = ((size_t)out_size >= (TILES_ELEMS + EXTRA_ELEMS)) ? 1 : 0;
        float* extra = out + TILES_ELEMS;
        fft_topk_gather_kernel<<<BN / 2, 256>>>(seqs, out, extra, write_extras);
    }
}